// round 2
// baseline (speedup 1.0000x reference)
#include <cuda_runtime.h>
#include <math.h>

#define Bn   4096
#define Nn   64
#define Dd   128
#define OCn  64
#define TPB  512

// Transposed GRU weights: [k][g] with g in 0..383 (r | z | n blocks of 128)
__device__ float g_WTih[Dd * 384];
__device__ float g_WThh[Dd * 384];

__global__ void prep_transpose(const float* __restrict__ W_ih,
                               const float* __restrict__ W_hh) {
    int idx = blockIdx.x * blockDim.x + threadIdx.x;   // over 384*128
    int total = 384 * Dd;
    if (idx < total) {
        int g = idx / Dd, k = idx % Dd;
        g_WTih[k * 384 + g] = W_ih[idx];
        g_WThh[k * 384 + g] = W_hh[idx];
    }
}

// ---------- packed f32x2 helpers (sm_103a: 2x FMA throughput vs 3-reg FFMA) ----------
__device__ __forceinline__ unsigned long long bcast2(float x) {
    unsigned long long r;
    asm("mov.b64 %0, {%1, %1};" : "=l"(r) : "f"(x));
    return r;
}
__device__ __forceinline__ void fma2(unsigned long long& d,
                                     unsigned long long a,
                                     unsigned long long b) {
    asm("fma.rn.f32x2 %0, %1, %2, %0;" : "+l"(d) : "l"(a), "l"(b));
}
__device__ __forceinline__ float2 unpack2(unsigned long long v) {
    float2 f;
    asm("mov.b64 {%0, %1}, %2;" : "=f"(f.x), "=f"(f.y) : "l"(v));
    return f;
}
__device__ __forceinline__ float sigmoidf_(float x) {
    return 1.f / (1.f + __expf(-x));
}

// C[4][4] (rows r0..r0+3, cols c0..c0+3) of:
//   oX = shX(64x128) @ W1(128 x LDW slice)      [cols taken at +c0 of given base]
//   oS = shS(64x128) @ W2(...)                  (only if DUAL)
template<int LDW, bool DUAL>
__device__ __forceinline__ void gemm4x4(const float* __restrict__ shX,
                                        const float* __restrict__ shS,
                                        const float* __restrict__ gW1,
                                        const float* __restrict__ gW2,
                                        int r0, int c0,
                                        float (&oX)[4][4], float (&oS)[4][4]) {
    unsigned long long aX[4][2], aS[4][2];
#pragma unroll
    for (int r = 0; r < 4; r++) {
        aX[r][0] = 0ull; aX[r][1] = 0ull;
        aS[r][0] = 0ull; aS[r][1] = 0ull;
    }
    const char* w1b = reinterpret_cast<const char*>(gW1 + c0);
    const char* w2b = DUAL ? reinterpret_cast<const char*>(gW2 + c0) : nullptr;

#pragma unroll 2
    for (int k0 = 0; k0 < Dd; k0 += 4) {
        float xv[4][4], sv[4][4];
#pragma unroll
        for (int r = 0; r < 4; r++) {
            float4 t = *reinterpret_cast<const float4*>(&shX[(r0 + r) * Dd + k0]);
            xv[r][0] = t.x; xv[r][1] = t.y; xv[r][2] = t.z; xv[r][3] = t.w;
            if constexpr (DUAL) {
                float4 u = *reinterpret_cast<const float4*>(&shS[(r0 + r) * Dd + k0]);
                sv[r][0] = u.x; sv[r][1] = u.y; sv[r][2] = u.z; sv[r][3] = u.w;
            }
        }
#pragma unroll
        for (int kk = 0; kk < 4; kk++) {
            ulonglong2 w1 = *reinterpret_cast<const ulonglong2*>(
                w1b + (size_t)(k0 + kk) * LDW * 4);
            ulonglong2 w2;
            if constexpr (DUAL)
                w2 = *reinterpret_cast<const ulonglong2*>(
                    w2b + (size_t)(k0 + kk) * LDW * 4);
#pragma unroll
            for (int r = 0; r < 4; r++) {
                unsigned long long xb = bcast2(xv[r][kk]);
                fma2(aX[r][0], xb, w1.x);
                fma2(aX[r][1], xb, w1.y);
                if constexpr (DUAL) {
                    unsigned long long sb = bcast2(sv[r][kk]);
                    fma2(aS[r][0], sb, w2.x);
                    fma2(aS[r][1], sb, w2.y);
                }
            }
        }
    }
#pragma unroll
    for (int r = 0; r < 4; r++) {
        float2 p0 = unpack2(aX[r][0]), p1 = unpack2(aX[r][1]);
        oX[r][0] = p0.x; oX[r][1] = p0.y; oX[r][2] = p1.x; oX[r][3] = p1.y;
        if constexpr (DUAL) {
            float2 q0 = unpack2(aS[r][0]), q1 = unpack2(aS[r][1]);
            oS[r][0] = q0.x; oS[r][1] = q0.y; oS[r][2] = q1.x; oS[r][3] = q1.y;
        }
    }
}

__global__ __launch_bounds__(TPB, 1)
void fignn_kernel(const float* __restrict__ h_g,
                  const float* __restrict__ a_src,
                  const float* __restrict__ a_dst,
                  const float* __restrict__ w_g,
                  const float* __restrict__ bias_g,
                  const float* __restrict__ b_ih,
                  const float* __restrict__ b_hh,
                  const float* __restrict__ mlp1_w,
                  const float* __restrict__ mlp1_b,
                  const float* __restrict__ mlp2_w,
                  const float* __restrict__ mlp2_b,
                  const int* __restrict__ steps_p,
                  float* __restrict__ out) {
    extern __shared__ float sm[];
    float* sh_h    = sm;               // 8192 floats
    float* sh_s    = sm + 8192;        // 8192
    float* sh_t1   = sm + 16384;       // 8192  (s@w, scratch for src/dst/wt/tk)
    float* sh_t2   = sm + 24576;       // 8192  (A = attn@(s@w)+bias)
    float* sh_attn = sm + 32768;       // 4096

    const int b    = blockIdx.x;
    const int tid  = threadIdx.x;
    const int lane = tid & 31;
    const int wid  = tid >> 5;
    const int c0   = lane * 4;         // cols 0..127
    const int r0   = wid * 4;          // rows 0..63

    const float* hb = h_g + (size_t)b * Nn * Dd;

    // load h -> shared; s = h
    for (int i = tid; i < Nn * Dd / 4; i += TPB) {
        float4 v = reinterpret_cast<const float4*>(hb)[i];
        reinterpret_cast<float4*>(sh_h)[i] = v;
        reinterpret_cast<float4*>(sh_s)[i] = v;
    }
    __syncthreads();

    // attn_src / attn_dst (stored in t1[0..63] / t1[64..127])
    if (tid < 128) {
        int i = tid & 63;
        const float* vec = (tid < 64) ? a_src : a_dst;
        float acc = 0.f;
#pragma unroll 8
        for (int k = 0; k < Dd; k++) acc += sh_h[i * Dd + k] * vec[k];
        sh_t1[(tid < 64 ? 0 : 64) + i] = acc;
    }
    __syncthreads();

    // attn rows: leaky_relu, zero diagonal (mask-multiply), softmax
    for (int row = wid; row < Nn; row += 16) {
        float srci = sh_t1[row];
        int j0 = lane, j1 = lane + 32;
        float v0 = srci + sh_t1[64 + j0];
        float v1 = srci + sh_t1[64 + j1];
        v0 = v0 > 0.f ? v0 : 0.2f * v0;
        v1 = v1 > 0.f ? v1 : 0.2f * v1;
        if (j0 == row) v0 = 0.f;
        if (j1 == row) v1 = 0.f;
        float m = fmaxf(v0, v1);
#pragma unroll
        for (int o = 16; o > 0; o >>= 1) m = fmaxf(m, __shfl_xor_sync(0xffffffffu, m, o));
        float e0 = __expf(v0 - m), e1 = __expf(v1 - m);
        float sum2 = e0 + e1;
#pragma unroll
        for (int o = 16; o > 0; o >>= 1) sum2 += __shfl_xor_sync(0xffffffffu, sum2, o);
        float inv = 1.f / sum2;
        sh_attn[row * Nn + j0] = e0 * inv;
        sh_attn[row * Nn + j1] = e1 * inv;
    }
    __syncthreads();

    int steps = steps_p ? *steps_p : 3;
    float dummy[4][4];

    for (int it = 0; it < steps; it++) {
        // ---- 1) t1 = s @ w ----
        float accw[4][4];
        gemm4x4<Dd, false>(sh_s, nullptr, w_g, nullptr, r0, c0, accw, dummy);
#pragma unroll
        for (int r = 0; r < 4; r++)
            *reinterpret_cast<float4*>(&sh_t1[(r0 + r) * Dd + c0]) =
                make_float4(accw[r][0], accw[r][1], accw[r][2], accw[r][3]);
        __syncthreads();

        // ---- 2) t2 = attn @ t1 + bias ----
        float acca[4][4] = {};
#pragma unroll 4
        for (int j = 0; j < Nn; j++) {
            float4 tv = *reinterpret_cast<const float4*>(&sh_t1[j * Dd + c0]);
#pragma unroll
            for (int r = 0; r < 4; r++) {
                float av = sh_attn[(r0 + r) * Nn + j];
                acca[r][0] += av * tv.x; acca[r][1] += av * tv.y;
                acca[r][2] += av * tv.z; acca[r][3] += av * tv.w;
            }
        }
        float4 bz = *reinterpret_cast<const float4*>(&bias_g[c0]);
#pragma unroll
        for (int r = 0; r < 4; r++)
            *reinterpret_cast<float4*>(&sh_t2[(r0 + r) * Dd + c0]) =
                make_float4(acca[r][0] + bz.x, acca[r][1] + bz.y,
                            acca[r][2] + bz.z, acca[r][3] + bz.w);
        __syncthreads();

        // ---- 3) GRU gates (R/Z kept in registers; same thread owns same cells) ----
        float gi[4][4], gh[4][4], Rr[4][4], Zz[4][4], Nv[4][4];

        // R gate: cols 0..127 of 384
        gemm4x4<384, true>(sh_t2, sh_s, g_WTih, g_WThh, r0, c0, gi, gh);
        {
            float4 bi = *reinterpret_cast<const float4*>(&b_ih[c0]);
            float4 bh = *reinterpret_cast<const float4*>(&b_hh[c0]);
            float bif[4] = {bi.x, bi.y, bi.z, bi.w};
            float bhf[4] = {bh.x, bh.y, bh.z, bh.w};
#pragma unroll
            for (int r = 0; r < 4; r++)
#pragma unroll
                for (int c = 0; c < 4; c++)
                    Rr[r][c] = sigmoidf_(gi[r][c] + bif[c] + gh[r][c] + bhf[c]);
        }
        // Z gate: cols 128..255
        gemm4x4<384, true>(sh_t2, sh_s, g_WTih + 128, g_WThh + 128, r0, c0, gi, gh);
        {
            float4 bi = *reinterpret_cast<const float4*>(&b_ih[128 + c0]);
            float4 bh = *reinterpret_cast<const float4*>(&b_hh[128 + c0]);
            float bif[4] = {bi.x, bi.y, bi.z, bi.w};
            float bhf[4] = {bh.x, bh.y, bh.z, bh.w};
#pragma unroll
            for (int r = 0; r < 4; r++)
#pragma unroll
                for (int c = 0; c < 4; c++)
                    Zz[r][c] = sigmoidf_(gi[r][c] + bif[c] + gh[r][c] + bhf[c]);
        }
        // N gate: cols 256..383 ; n = tanh(i_n + r * h_n)
        gemm4x4<384, true>(sh_t2, sh_s, g_WTih + 256, g_WThh + 256, r0, c0, gi, gh);
        {
            float4 bi = *reinterpret_cast<const float4*>(&b_ih[256 + c0]);
            float4 bh = *reinterpret_cast<const float4*>(&b_hh[256 + c0]);
            float bif[4] = {bi.x, bi.y, bi.z, bi.w};
            float bhf[4] = {bh.x, bh.y, bh.z, bh.w};
#pragma unroll
            for (int r = 0; r < 4; r++)
#pragma unroll
                for (int c = 0; c < 4; c++)
                    Nv[r][c] = tanhf(gi[r][c] + bif[c] +
                                     Rr[r][c] * (gh[r][c] + bhf[c]));
        }

        // ---- 4) s = (1-z)*n + z*s + h  (barrier: all gemm reads of s done first) ----
        float sold[4][4], hold[4][4];
#pragma unroll
        for (int r = 0; r < 4; r++) {
            float4 so = *reinterpret_cast<const float4*>(&sh_s[(r0 + r) * Dd + c0]);
            float4 ho = *reinterpret_cast<const float4*>(&sh_h[(r0 + r) * Dd + c0]);
            sold[r][0] = so.x; sold[r][1] = so.y; sold[r][2] = so.z; sold[r][3] = so.w;
            hold[r][0] = ho.x; hold[r][1] = ho.y; hold[r][2] = ho.z; hold[r][3] = ho.w;
        }
        __syncthreads();
#pragma unroll
        for (int r = 0; r < 4; r++) {
            float v[4];
#pragma unroll
            for (int c = 0; c < 4; c++)
                v[c] = (1.f - Zz[r][c]) * Nv[r][c] + Zz[r][c] * sold[r][c] + hold[r][c];
            *reinterpret_cast<float4*>(&sh_s[(r0 + r) * Dd + c0]) =
                make_float4(v[0], v[1], v[2], v[3]);
        }
        __syncthreads();
    }

    // ---- readout: out[c] = sum_k (sum_n wt[n]*s[n][k]) * mlp1_w[k][c] + (sum wt)*mlp1_b[c]
    if (tid < Nn) {
        float acc = 0.f;
#pragma unroll 8
        for (int k = 0; k < Dd; k++) acc += sh_s[tid * Dd + k] * mlp2_w[k];
        sh_t1[tid] = acc + mlp2_b[0];
    }
    __syncthreads();
    if (tid < Dd) {
        float acc = 0.f;
#pragma unroll
        for (int n = 0; n < Nn; n++) acc += sh_t1[n] * sh_s[n * Dd + tid];
        sh_t1[128 + tid] = acc;
    }
    __syncthreads();
    if (tid < OCn) {
        float acc = 0.f;
#pragma unroll 4
        for (int k = 0; k < Dd; k++) acc += sh_t1[128 + k] * mlp1_w[k * OCn + tid];
        float wsum = 0.f;
#pragma unroll
        for (int n = 0; n < Nn; n++) wsum += sh_t1[n];
        out[(size_t)b * OCn + tid] = acc + wsum * mlp1_b[tid];
    }
}

extern "C" void kernel_launch(void* const* d_in, const int* in_sizes, int n_in,
                              void* d_out, int out_size) {
    const float* h      = (const float*)d_in[0];
    // d_in[1] = adj : unused by the reference math (only its shape is used)
    const float* a_src  = (const float*)d_in[2];
    const float* a_dst  = (const float*)d_in[3];
    const float* w      = (const float*)d_in[4];
    const float* bias   = (const float*)d_in[5];
    const float* W_ih   = (const float*)d_in[6];
    const float* W_hh   = (const float*)d_in[7];
    const float* b_ih   = (const float*)d_in[8];
    const float* b_hh   = (const float*)d_in[9];
    const float* mlp1_w = (const float*)d_in[10];
    const float* mlp1_b = (const float*)d_in[11];
    const float* mlp2_w = (const float*)d_in[12];
    const float* mlp2_b = (const float*)d_in[13];
    const int*   steps  = (n_in > 14) ? (const int*)d_in[14] : nullptr;

    int batches = in_sizes[0] / (Nn * Dd);

    cudaFuncSetAttribute(fignn_kernel,
                         cudaFuncAttributeMaxDynamicSharedMemorySize, 147456);

    prep_transpose<<<(384 * Dd + 255) / 256, 256>>>(W_ih, W_hh);
    fignn_kernel<<<batches, TPB, 147456>>>(h, a_src, a_dst, w, bias,
                                           b_ih, b_hh, mlp1_w, mlp1_b,
                                           mlp2_w, mlp2_b, steps,
                                           (float*)d_out);
}